// round 11
// baseline (speedup 1.0000x reference)
#include <cuda_runtime.h>
#include <math.h>

#define D      128
#define ROWS   32            // rows per block in kernel 1 (static smem fits)
#define NBLK1  256           // 8192 / 32
#define TPB    256
#define NJOBS  528           // 136 (Gq upper) + 136 (Gk upper) + 256 (C full)
#define CBLK   64            // combine grid
#define EPS    1e-8f

typedef unsigned long long u64;

// Deterministic scratch (no atomics on float, no allocation):
// Strict-lower tiles of g_part[0]/g_part[1] are never written AND never read.
__device__ float g_part[3][NBLK1][D * D];   // 50.3 MB (L2-resident)
__device__ float g_diag[NBLK1];             // per-block diagonal correction
__device__ float g_bsum[CBLK];              // combine-block sums
__device__ int   g_count;                   // last-block counter (self-resetting)

// ---- packed fp32x2 helpers (Blackwell FFMA2) -------------------------------
__device__ __forceinline__ u64 pack2(float lo, float hi) {
    u64 r; asm("mov.b64 %0, {%1, %2};" : "=l"(r) : "f"(lo), "f"(hi)); return r;
}
__device__ __forceinline__ void unpack2(u64 v, float& lo, float& hi) {
    asm("mov.b64 {%0, %1}, %2;" : "=f"(lo), "=f"(hi) : "l"(v));
}
__device__ __forceinline__ u64 ffma2(u64 a, u64 b, u64 c) {
    u64 d; asm("fma.rn.f32x2 %0, %1, %2, %3;" : "=l"(d) : "l"(a), "l"(b), "l"(c));
    return d;
}

// ---------------------------------------------------------------------------
// Kernel 1 (unchanged from R10 measurement): per-block partial Grams.
//   Gq = Qn^T Qn (upper tiles), Gk = Kn^T Kn (upper tiles), C = Qn^T Kn (full)
// ---------------------------------------------------------------------------
__global__ __launch_bounds__(TPB, 2) void gram_partial_kernel(
    const float* __restrict__ q, const float* __restrict__ k)
{
    __shared__ float qs[ROWS][D];
    __shared__ float ks[ROWS][D];
    __shared__ float s_invq[ROWS], s_invk[ROWS];
    __shared__ float s_tq[ROWS],   s_tk[ROWS];

    const int tid = threadIdx.x;
    const int bid = blockIdx.x;

    const float4* q4 = (const float4*)(q + (size_t)bid * ROWS * D);
    const float4* k4 = (const float4*)(k + (size_t)bid * ROWS * D);
    float4* qs4 = (float4*)&qs[0][0];
    float4* ks4 = (float4*)&ks[0][0];
    const int NV = ROWS * D / 4;  // 1024
    #pragma unroll
    for (int i = tid; i < NV; i += TPB) { qs4[i] = q4[i]; ks4[i] = k4[i]; }
    __syncthreads();

    {
        const int w = tid >> 5, lane = tid & 31;
        #pragma unroll
        for (int r4 = 0; r4 < 4; r4++) {
            const int r = w * 4 + r4;
            float sq = 0.f, sk_ = 0.f;
            #pragma unroll
            for (int c = lane; c < D; c += 32) {
                float a = qs[r][c]; sq  = fmaf(a, a, sq);
                float b = ks[r][c]; sk_ = fmaf(b, b, sk_);
            }
            #pragma unroll
            for (int o = 16; o; o >>= 1) {
                sq  += __shfl_xor_sync(0xffffffffu, sq,  o);
                sk_ += __shfl_xor_sync(0xffffffffu, sk_, o);
            }
            if (lane == 0) {
                float nq = sqrtf(sq), nk = sqrtf(sk_);
                float iq = 1.0f / fmaxf(nq, EPS);
                float ik = 1.0f / fmaxf(nk, EPS);
                s_invq[r] = iq; s_invk[r] = ik;
                float tq = nq * iq, tk = nk * ik;
                s_tq[r] = tq * tq; s_tk[r] = tk * tk;
            }
        }
    }
    __syncthreads();

    #pragma unroll
    for (int i = tid; i < NV; i += TPB) {
        const int r = i >> 5;
        float4 v = qs4[i]; const float s = s_invq[r];
        v.x *= s; v.y *= s; v.z *= s; v.w *= s; qs4[i] = v;
        float4 u = ks4[i]; const float t = s_invk[r];
        u.x *= t; u.y *= t; u.z *= t; u.w *= t; ks4[i] = u;
    }
    __syncthreads();

    if (tid == 0) {
        float dsum = 0.f;
        #pragma unroll
        for (int r = 0; r < ROWS; r++) {
            float d = s_tq[r] - s_tk[r];
            dsum = fmaf(d, d, dsum);
        }
        g_diag[bid] = dsum;
    }

    #pragma unroll 1
    for (int p = 0; p < 3; p++) {
        const int u = p * TPB + tid;
        if (u >= NJOBS) continue;

        int mat, i0, j0;
        if (u < 272) {
            mat = (u < 136) ? 0 : 1;
            int idx = u - mat * 136;
            int i = 0;
            while (idx >= 16 - i) { idx -= 16 - i; i++; }
            i0 = i; j0 = i + idx;
        } else {
            mat = 2;
            const int v = u - 272;
            i0 = v >> 4; j0 = v & 15;
        }

        const float (*A)[D] = (mat == 1) ? ks : qs;
        const float (*B)[D] = (mat == 0) ? qs : ks;
        const int a0 = i0 * 4, b0 = j0 * 4;

        u64 acc[8][4];
        #pragma unroll
        for (int i = 0; i < 8; i++)
            #pragma unroll
            for (int j = 0; j < 4; j++) acc[i][j] = 0ull;

        #pragma unroll 4
        for (int r = 0; r < ROWS; r++) {
            float4 alo = *(const float4*)&A[r][a0];
            float4 ahi = *(const float4*)&A[r][a0 + 64];
            float4 blo = *(const float4*)&B[r][b0];
            float4 bhi = *(const float4*)&B[r][b0 + 64];
            float ra[8] = {alo.x, alo.y, alo.z, alo.w, ahi.x, ahi.y, ahi.z, ahi.w};
            u64 rb2[4] = {pack2(blo.x, blo.y), pack2(blo.z, blo.w),
                          pack2(bhi.x, bhi.y), pack2(bhi.z, bhi.w)};
            #pragma unroll
            for (int i = 0; i < 8; i++) {
                u64 ad = pack2(ra[i], ra[i]);
                #pragma unroll
                for (int j = 0; j < 4; j++)
                    acc[i][j] = ffma2(ad, rb2[j], acc[i][j]);
            }
        }

        float* out = &g_part[mat][bid][0];
        #pragma unroll
        for (int i = 0; i < 8; i++) {
            const int row = (i < 4) ? (a0 + i) : (64 + a0 + i - 4);
            float4 v;
            unpack2(acc[i][0], v.x, v.y); unpack2(acc[i][1], v.z, v.w);
            *(float4*)&out[row * D + b0] = v;
            unpack2(acc[i][2], v.x, v.y); unpack2(acc[i][3], v.z, v.w);
            *(float4*)&out[row * D + b0 + 64] = v;
        }
    }
}

// ---------------------------------------------------------------------------
// Kernel 2 (fused combine + final): float4 per thread-quartet, zero-tile skip.
//   Each quartet owns 4 consecutive entries e0..e0+3 (same tile -> same w,
//   same have_g); 4-way b-split across quartet lanes; LDG.128 loads.
//   contrib = w*(|Gq|^2+|Gk|^2) - 2|C|^2 summed exactly once per entry.
//   Last block (atomic counter) merges block sums, subtracts diag, writes out.
// ---------------------------------------------------------------------------
__global__ __launch_bounds__(TPB) void combine_kernel(float* __restrict__ out,
                                                      int n)
{
    const int tid  = threadIdx.x;
    const int qidx = (blockIdx.x * TPB + tid) >> 2;   // 0..4095
    const int e0   = qidx * 4;                        // aligned 4-entry group
    const int r    = e0 >> 7, c0 = e0 & 127;
    const int i0   = (r & 63) >> 2, j0 = (c0 & 63) >> 2;
    const bool have_g = (i0 <= j0);                   // Gq/Gk tile stored?
    const float w  = (i0 == j0) ? 1.0f : 2.0f;
    const int bq   = (tid & 3) * (NBLK1 / 4);         // this lane's b-quarter

    float4 sq = make_float4(0.f, 0.f, 0.f, 0.f);
    float4 sk = sq, sc = sq;
    #pragma unroll 4
    for (int bb = 0; bb < NBLK1 / 4; bb++) {
        const int b = bq + bb;
        if (have_g) {
            float4 a = *(const float4*)&g_part[0][b][e0];
            float4 d = *(const float4*)&g_part[1][b][e0];
            sq.x += a.x; sq.y += a.y; sq.z += a.z; sq.w += a.w;
            sk.x += d.x; sk.y += d.y; sk.z += d.z; sk.w += d.w;
        }
        float4 cc = *(const float4*)&g_part[2][b][e0];
        sc.x += cc.x; sc.y += cc.y; sc.z += cc.z; sc.w += cc.w;
    }

    // combine the 4 b-quarter partials within each quartet (bits 0,1)
    #pragma unroll
    for (int o = 1; o <= 2; o <<= 1) {
        sq.x += __shfl_xor_sync(0xffffffffu, sq.x, o);
        sq.y += __shfl_xor_sync(0xffffffffu, sq.y, o);
        sq.z += __shfl_xor_sync(0xffffffffu, sq.z, o);
        sq.w += __shfl_xor_sync(0xffffffffu, sq.w, o);
        sk.x += __shfl_xor_sync(0xffffffffu, sk.x, o);
        sk.y += __shfl_xor_sync(0xffffffffu, sk.y, o);
        sk.z += __shfl_xor_sync(0xffffffffu, sk.z, o);
        sk.w += __shfl_xor_sync(0xffffffffu, sk.w, o);
        sc.x += __shfl_xor_sync(0xffffffffu, sc.x, o);
        sc.y += __shfl_xor_sync(0xffffffffu, sc.y, o);
        sc.z += __shfl_xor_sync(0xffffffffu, sc.z, o);
        sc.w += __shfl_xor_sync(0xffffffffu, sc.w, o);
    }

    float gg = sq.x * sq.x + sq.y * sq.y + sq.z * sq.z + sq.w * sq.w
             + sk.x * sk.x + sk.y * sk.y + sk.z * sk.z + sk.w * sk.w;
    float cc2 = sc.x * sc.x + sc.y * sc.y + sc.z * sc.z + sc.w * sc.w;
    float contrib = w * gg - 2.0f * cc2;

    // one lane per quartet counts once: butterfly over bits 2..4
    #pragma unroll
    for (int o = 4; o <= 16; o <<= 1)
        contrib += __shfl_xor_sync(0xffffffffu, contrib, o);

    __shared__ float red[8];
    __shared__ int   s_last;
    const int lane = tid & 31, wrp = tid >> 5;
    if (lane == 0) red[wrp] = contrib;
    __syncthreads();
    if (wrp == 0) {
        float v = (lane < 8) ? red[lane] : 0.f;
        #pragma unroll
        for (int o = 4; o; o >>= 1) v += __shfl_xor_sync(0xffffffffu, v, o);
        if (lane == 0) g_bsum[blockIdx.x] = v;
    }
    __syncthreads();

    // last-block final reduction (deterministic: fixed read order)
    if (tid == 0) {
        __threadfence();
        s_last = (atomicAdd(&g_count, 1) == CBLK - 1);
    }
    __syncthreads();
    if (s_last) {
        __threadfence();
        float v = (tid < CBLK) ? g_bsum[tid] : 0.f;
        v -= g_diag[tid];                      // 256 diag partials
        #pragma unroll
        for (int o = 16; o; o >>= 1) v += __shfl_xor_sync(0xffffffffu, v, o);
        if (lane == 0) red[wrp] = v;
        __syncthreads();
        if (wrp == 0) {
            float x = (lane < 8) ? red[lane] : 0.f;
            #pragma unroll
            for (int o = 4; o; o >>= 1) x += __shfl_xor_sync(0xffffffffu, x, o);
            if (lane == 0) {
                double denom = (double)n * (double)(n - 1);
                out[0] = (float)((double)x / denom);
                g_count = 0;                   // reset for next graph replay
            }
        }
    }
}

// ---------------------------------------------------------------------------
extern "C" void kernel_launch(void* const* d_in, const int* in_sizes, int n_in,
                              void* d_out, int out_size)
{
    const float* q = (const float*)d_in[0];
    const float* k = (const float*)d_in[1];
    const int n = in_sizes[0] / D;        // 8192

    gram_partial_kernel<<<n / ROWS, TPB>>>(q, k);
    combine_kernel<<<CBLK, TPB>>>((float*)d_out, n);
}

// round 13
// speedup vs baseline: 1.2170x; 1.2170x over previous
#include <cuda_runtime.h>
#include <math.h>

#define D      128
#define ROWS   32            // rows per block in kernel 1 (static smem fits)
#define NBLK1  256           // 8192 / 32
#define TPB    256
#define NJOBS  528           // 136 (Gq upper) + 136 (Gk upper) + 256 (C full)
#define CBLK   256           // combine grid (65536 threads, 16 per entry-group)
#define EPS    1e-8f

typedef unsigned long long u64;

// Deterministic scratch (no float atomics, no allocation):
// Strict-lower tiles of g_part[0]/g_part[1] are never written AND never read.
__device__ float g_part[3][NBLK1][D * D];   // 50.3 MB
__device__ float g_diag[NBLK1];             // per-block diagonal correction
__device__ float g_bsum[CBLK];              // combine-block sums
__device__ int   g_count;                   // last-block counter (self-resetting)

// ---- packed fp32x2 helpers (Blackwell FFMA2) -------------------------------
__device__ __forceinline__ u64 pack2(float lo, float hi) {
    u64 r; asm("mov.b64 %0, {%1, %2};" : "=l"(r) : "f"(lo), "f"(hi)); return r;
}
__device__ __forceinline__ void unpack2(u64 v, float& lo, float& hi) {
    asm("mov.b64 {%0, %1}, %2;" : "=f"(lo), "=f"(hi) : "l"(v));
}
__device__ __forceinline__ u64 ffma2(u64 a, u64 b, u64 c) {
    u64 d; asm("fma.rn.f32x2 %0, %1, %2, %3;" : "=l"(d) : "l"(a), "l"(b), "l"(c));
    return d;
}

// ---------------------------------------------------------------------------
// Kernel 1 (unchanged since R10 measurement): per-block partial Grams.
//   Gq = Qn^T Qn (upper tiles), Gk = Kn^T Kn (upper tiles), C = Qn^T Kn (full)
// ---------------------------------------------------------------------------
__global__ __launch_bounds__(TPB, 2) void gram_partial_kernel(
    const float* __restrict__ q, const float* __restrict__ k)
{
    __shared__ float qs[ROWS][D];
    __shared__ float ks[ROWS][D];
    __shared__ float s_invq[ROWS], s_invk[ROWS];
    __shared__ float s_tq[ROWS],   s_tk[ROWS];

    const int tid = threadIdx.x;
    const int bid = blockIdx.x;

    const float4* q4 = (const float4*)(q + (size_t)bid * ROWS * D);
    const float4* k4 = (const float4*)(k + (size_t)bid * ROWS * D);
    float4* qs4 = (float4*)&qs[0][0];
    float4* ks4 = (float4*)&ks[0][0];
    const int NV = ROWS * D / 4;  // 1024
    #pragma unroll
    for (int i = tid; i < NV; i += TPB) { qs4[i] = q4[i]; ks4[i] = k4[i]; }
    __syncthreads();

    {
        const int w = tid >> 5, lane = tid & 31;
        #pragma unroll
        for (int r4 = 0; r4 < 4; r4++) {
            const int r = w * 4 + r4;
            float sq = 0.f, sk_ = 0.f;
            #pragma unroll
            for (int c = lane; c < D; c += 32) {
                float a = qs[r][c]; sq  = fmaf(a, a, sq);
                float b = ks[r][c]; sk_ = fmaf(b, b, sk_);
            }
            #pragma unroll
            for (int o = 16; o; o >>= 1) {
                sq  += __shfl_xor_sync(0xffffffffu, sq,  o);
                sk_ += __shfl_xor_sync(0xffffffffu, sk_, o);
            }
            if (lane == 0) {
                float nq = sqrtf(sq), nk = sqrtf(sk_);
                float iq = 1.0f / fmaxf(nq, EPS);
                float ik = 1.0f / fmaxf(nk, EPS);
                s_invq[r] = iq; s_invk[r] = ik;
                float tq = nq * iq, tk = nk * ik;
                s_tq[r] = tq * tq; s_tk[r] = tk * tk;
            }
        }
    }
    __syncthreads();

    #pragma unroll
    for (int i = tid; i < NV; i += TPB) {
        const int r = i >> 5;
        float4 v = qs4[i]; const float s = s_invq[r];
        v.x *= s; v.y *= s; v.z *= s; v.w *= s; qs4[i] = v;
        float4 u = ks4[i]; const float t = s_invk[r];
        u.x *= t; u.y *= t; u.z *= t; u.w *= t; ks4[i] = u;
    }
    __syncthreads();

    if (tid == 0) {
        float dsum = 0.f;
        #pragma unroll
        for (int r = 0; r < ROWS; r++) {
            float d = s_tq[r] - s_tk[r];
            dsum = fmaf(d, d, dsum);
        }
        g_diag[bid] = dsum;
    }

    #pragma unroll 1
    for (int p = 0; p < 3; p++) {
        const int u = p * TPB + tid;
        if (u >= NJOBS) continue;

        int mat, i0, j0;
        if (u < 272) {
            mat = (u < 136) ? 0 : 1;
            int idx = u - mat * 136;
            int i = 0;
            while (idx >= 16 - i) { idx -= 16 - i; i++; }
            i0 = i; j0 = i + idx;
        } else {
            mat = 2;
            const int v = u - 272;
            i0 = v >> 4; j0 = v & 15;
        }

        const float (*A)[D] = (mat == 1) ? ks : qs;
        const float (*B)[D] = (mat == 0) ? qs : ks;
        const int a0 = i0 * 4, b0 = j0 * 4;

        u64 acc[8][4];
        #pragma unroll
        for (int i = 0; i < 8; i++)
            #pragma unroll
            for (int j = 0; j < 4; j++) acc[i][j] = 0ull;

        #pragma unroll 4
        for (int r = 0; r < ROWS; r++) {
            float4 alo = *(const float4*)&A[r][a0];
            float4 ahi = *(const float4*)&A[r][a0 + 64];
            float4 blo = *(const float4*)&B[r][b0];
            float4 bhi = *(const float4*)&B[r][b0 + 64];
            float ra[8] = {alo.x, alo.y, alo.z, alo.w, ahi.x, ahi.y, ahi.z, ahi.w};
            u64 rb2[4] = {pack2(blo.x, blo.y), pack2(blo.z, blo.w),
                          pack2(bhi.x, bhi.y), pack2(bhi.z, bhi.w)};
            #pragma unroll
            for (int i = 0; i < 8; i++) {
                u64 ad = pack2(ra[i], ra[i]);
                #pragma unroll
                for (int j = 0; j < 4; j++)
                    acc[i][j] = ffma2(ad, rb2[j], acc[i][j]);
            }
        }

        float* out = &g_part[mat][bid][0];
        #pragma unroll
        for (int i = 0; i < 8; i++) {
            const int row = (i < 4) ? (a0 + i) : (64 + a0 + i - 4);
            float4 v;
            unpack2(acc[i][0], v.x, v.y); unpack2(acc[i][1], v.z, v.w);
            *(float4*)&out[row * D + b0] = v;
            unpack2(acc[i][2], v.x, v.y); unpack2(acc[i][3], v.z, v.w);
            *(float4*)&out[row * D + b0 + 64] = v;
        }
    }
}

// ---------------------------------------------------------------------------
// Kernel 2 (fused combine + final), re-parallelized:
//   4096 entry-groups (float4 each) x 16 threads (b-split 16 ways)
//   = 65536 threads = 256 CTAs. Each thread: 16 independent LDG.128 triples
//   (MLP ~48). Butterfly bits 0..3 merges b-partials; offset-16 butterfly
//   counts the warp's 2 groups exactly once. Zero-tile skip for Gq/Gk.
//   Last block (atomic counter) merges block sums, subtracts diag, writes out.
// ---------------------------------------------------------------------------
__global__ __launch_bounds__(TPB) void combine_kernel(float* __restrict__ out,
                                                      int n)
{
    const int tid = threadIdx.x;
    const int gt  = blockIdx.x * TPB + tid;          // 0..65535
    const int gid = gt >> 4;                         // entry-group 0..4095
    const int e0  = gid * 4;                         // aligned 4-entry group
    const int sub = gt & 15;                         // b-sixteenth
    const int r   = e0 >> 7, c0 = e0 & 127;
    const int i0  = (r & 63) >> 2, j0 = (c0 & 63) >> 2;
    const bool have_g = (i0 <= j0);                  // Gq/Gk tile stored?
    const float w = (i0 == j0) ? 1.0f : 2.0f;
    const int bbase = sub * (NBLK1 / 16);            // 16 blocks per thread

    float4 sq = make_float4(0.f, 0.f, 0.f, 0.f);
    float4 sk = sq, sc = sq;
    #pragma unroll
    for (int bb = 0; bb < NBLK1 / 16; bb++) {
        const int b = bbase + bb;
        if (have_g) {
            float4 a = *(const float4*)&g_part[0][b][e0];
            float4 d = *(const float4*)&g_part[1][b][e0];
            sq.x += a.x; sq.y += a.y; sq.z += a.z; sq.w += a.w;
            sk.x += d.x; sk.y += d.y; sk.z += d.z; sk.w += d.w;
        }
        float4 cc = *(const float4*)&g_part[2][b][e0];
        sc.x += cc.x; sc.y += cc.y; sc.z += cc.z; sc.w += cc.w;
    }

    // merge the 16 b-partials of this group (butterfly bits 0..3)
    #pragma unroll
    for (int o = 1; o <= 8; o <<= 1) {
        sq.x += __shfl_xor_sync(0xffffffffu, sq.x, o);
        sq.y += __shfl_xor_sync(0xffffffffu, sq.y, o);
        sq.z += __shfl_xor_sync(0xffffffffu, sq.z, o);
        sq.w += __shfl_xor_sync(0xffffffffu, sq.w, o);
        sk.x += __shfl_xor_sync(0xffffffffu, sk.x, o);
        sk.y += __shfl_xor_sync(0xffffffffu, sk.y, o);
        sk.z += __shfl_xor_sync(0xffffffffu, sk.z, o);
        sk.w += __shfl_xor_sync(0xffffffffu, sk.w, o);
        sc.x += __shfl_xor_sync(0xffffffffu, sc.x, o);
        sc.y += __shfl_xor_sync(0xffffffffu, sc.y, o);
        sc.z += __shfl_xor_sync(0xffffffffu, sc.z, o);
        sc.w += __shfl_xor_sync(0xffffffffu, sc.w, o);
    }

    float gg = sq.x * sq.x + sq.y * sq.y + sq.z * sq.z + sq.w * sq.w
             + sk.x * sk.x + sk.y * sk.y + sk.z * sk.z + sk.w * sk.w;
    float cc2 = sc.x * sc.x + sc.y * sc.y + sc.z * sc.z + sc.w * sc.w;
    float contrib = w * gg - 2.0f * cc2;

    // the warp holds 2 groups (16 identical lanes each): offset-16 butterfly
    // gives every lane groupA+groupB, counted exactly once via lane 0.
    contrib += __shfl_xor_sync(0xffffffffu, contrib, 16);

    __shared__ float red[8];
    __shared__ int   s_last;
    const int lane = tid & 31, wrp = tid >> 5;
    if (lane == 0) red[wrp] = contrib;
    __syncthreads();
    if (wrp == 0) {
        float v = (lane < 8) ? red[lane] : 0.f;
        #pragma unroll
        for (int o = 4; o; o >>= 1) v += __shfl_xor_sync(0xffffffffu, v, o);
        if (lane == 0) g_bsum[blockIdx.x] = v;
    }
    __syncthreads();

    // last-block final reduction (deterministic: fixed read order)
    if (tid == 0) {
        __threadfence();
        s_last = (atomicAdd(&g_count, 1) == CBLK - 1);
    }
    __syncthreads();
    if (s_last) {
        __threadfence();
        float v = g_bsum[tid] - g_diag[tid];        // 256 each
        #pragma unroll
        for (int o = 16; o; o >>= 1) v += __shfl_xor_sync(0xffffffffu, v, o);
        if (lane == 0) red[wrp] = v;
        __syncthreads();
        if (wrp == 0) {
            float x = (lane < 8) ? red[lane] : 0.f;
            #pragma unroll
            for (int o = 4; o; o >>= 1) x += __shfl_xor_sync(0xffffffffu, x, o);
            if (lane == 0) {
                double denom = (double)n * (double)(n - 1);
                out[0] = (float)((double)x / denom);
                g_count = 0;                        // reset for next replay
            }
        }
    }
}

// ---------------------------------------------------------------------------
extern "C" void kernel_launch(void* const* d_in, const int* in_sizes, int n_in,
                              void* d_out, int out_size)
{
    const float* q = (const float*)d_in[0];
    const float* k = (const float*)d_in[1];
    const int n = in_sizes[0] / D;        // 8192

    gram_partial_kernel<<<n / ROWS, TPB>>>(q, k);
    combine_kernel<<<CBLK, TPB>>>((float*)d_out, n);
}

// round 15
// speedup vs baseline: 1.4562x; 1.1965x over previous
#include <cuda_runtime.h>
#include <math.h>

#define D      128
#define ROWS   32            // rows per block in kernel 1 (static smem fits)
#define NBLK1  256           // 8192 / 32
#define TPB    256
#define NJOBS  528           // 136 (Gq upper) + 136 (Gk upper) + 256 (C full)
#define CBLK   512           // combine grid: one CTA per 32-entry window
#define EPS    1e-8f

typedef unsigned long long u64;

// Deterministic scratch (no float atomics, no allocation):
// Strict-lower tiles of g_part[0]/g_part[1] are never written AND never read.
__device__ float g_part[3][NBLK1][D * D];   // 50.3 MB
__device__ float g_diag[NBLK1];             // per-block diagonal correction
__device__ float g_bsum[CBLK];              // combine-block sums
__device__ int   g_count;                   // last-block counter (self-resetting)

// ---- packed fp32x2 helpers (Blackwell FFMA2) -------------------------------
__device__ __forceinline__ u64 pack2(float lo, float hi) {
    u64 r; asm("mov.b64 %0, {%1, %2};" : "=l"(r) : "f"(lo), "f"(hi)); return r;
}
__device__ __forceinline__ void unpack2(u64 v, float& lo, float& hi) {
    asm("mov.b64 {%0, %1}, %2;" : "=f"(lo), "=f"(hi) : "l"(v));
}
__device__ __forceinline__ u64 ffma2(u64 a, u64 b, u64 c) {
    u64 d; asm("fma.rn.f32x2 %0, %1, %2, %3;" : "=l"(d) : "l"(a), "l"(b), "l"(c));
    return d;
}

// ---------------------------------------------------------------------------
// Kernel 1 (unchanged since R10 measurement): per-block partial Grams.
//   Gq = Qn^T Qn (upper tiles), Gk = Kn^T Kn (upper tiles), C = Qn^T Kn (full)
// ---------------------------------------------------------------------------
__global__ __launch_bounds__(TPB, 2) void gram_partial_kernel(
    const float* __restrict__ q, const float* __restrict__ k)
{
    __shared__ float qs[ROWS][D];
    __shared__ float ks[ROWS][D];
    __shared__ float s_invq[ROWS], s_invk[ROWS];
    __shared__ float s_tq[ROWS],   s_tk[ROWS];

    const int tid = threadIdx.x;
    const int bid = blockIdx.x;

    const float4* q4 = (const float4*)(q + (size_t)bid * ROWS * D);
    const float4* k4 = (const float4*)(k + (size_t)bid * ROWS * D);
    float4* qs4 = (float4*)&qs[0][0];
    float4* ks4 = (float4*)&ks[0][0];
    const int NV = ROWS * D / 4;  // 1024
    #pragma unroll
    for (int i = tid; i < NV; i += TPB) { qs4[i] = q4[i]; ks4[i] = k4[i]; }
    __syncthreads();

    {
        const int w = tid >> 5, lane = tid & 31;
        #pragma unroll
        for (int r4 = 0; r4 < 4; r4++) {
            const int r = w * 4 + r4;
            float sq = 0.f, sk_ = 0.f;
            #pragma unroll
            for (int c = lane; c < D; c += 32) {
                float a = qs[r][c]; sq  = fmaf(a, a, sq);
                float b = ks[r][c]; sk_ = fmaf(b, b, sk_);
            }
            #pragma unroll
            for (int o = 16; o; o >>= 1) {
                sq  += __shfl_xor_sync(0xffffffffu, sq,  o);
                sk_ += __shfl_xor_sync(0xffffffffu, sk_, o);
            }
            if (lane == 0) {
                float nq = sqrtf(sq), nk = sqrtf(sk_);
                float iq = 1.0f / fmaxf(nq, EPS);
                float ik = 1.0f / fmaxf(nk, EPS);
                s_invq[r] = iq; s_invk[r] = ik;
                float tq = nq * iq, tk = nk * ik;
                s_tq[r] = tq * tq; s_tk[r] = tk * tk;
            }
        }
    }
    __syncthreads();

    #pragma unroll
    for (int i = tid; i < NV; i += TPB) {
        const int r = i >> 5;
        float4 v = qs4[i]; const float s = s_invq[r];
        v.x *= s; v.y *= s; v.z *= s; v.w *= s; qs4[i] = v;
        float4 u = ks4[i]; const float t = s_invk[r];
        u.x *= t; u.y *= t; u.z *= t; u.w *= t; ks4[i] = u;
    }
    __syncthreads();

    if (tid == 0) {
        float dsum = 0.f;
        #pragma unroll
        for (int r = 0; r < ROWS; r++) {
            float d = s_tq[r] - s_tk[r];
            dsum = fmaf(d, d, dsum);
        }
        g_diag[bid] = dsum;
    }

    #pragma unroll 1
    for (int p = 0; p < 3; p++) {
        const int u = p * TPB + tid;
        if (u >= NJOBS) continue;

        int mat, i0, j0;
        if (u < 272) {
            mat = (u < 136) ? 0 : 1;
            int idx = u - mat * 136;
            int i = 0;
            while (idx >= 16 - i) { idx -= 16 - i; i++; }
            i0 = i; j0 = i + idx;
        } else {
            mat = 2;
            const int v = u - 272;
            i0 = v >> 4; j0 = v & 15;
        }

        const float (*A)[D] = (mat == 1) ? ks : qs;
        const float (*B)[D] = (mat == 0) ? qs : ks;
        const int a0 = i0 * 4, b0 = j0 * 4;

        u64 acc[8][4];
        #pragma unroll
        for (int i = 0; i < 8; i++)
            #pragma unroll
            for (int j = 0; j < 4; j++) acc[i][j] = 0ull;

        #pragma unroll 4
        for (int r = 0; r < ROWS; r++) {
            float4 alo = *(const float4*)&A[r][a0];
            float4 ahi = *(const float4*)&A[r][a0 + 64];
            float4 blo = *(const float4*)&B[r][b0];
            float4 bhi = *(const float4*)&B[r][b0 + 64];
            float ra[8] = {alo.x, alo.y, alo.z, alo.w, ahi.x, ahi.y, ahi.z, ahi.w};
            u64 rb2[4] = {pack2(blo.x, blo.y), pack2(blo.z, blo.w),
                          pack2(bhi.x, bhi.y), pack2(bhi.z, bhi.w)};
            #pragma unroll
            for (int i = 0; i < 8; i++) {
                u64 ad = pack2(ra[i], ra[i]);
                #pragma unroll
                for (int j = 0; j < 4; j++)
                    acc[i][j] = ffma2(ad, rb2[j], acc[i][j]);
            }
        }

        float* out = &g_part[mat][bid][0];
        #pragma unroll
        for (int i = 0; i < 8; i++) {
            const int row = (i < 4) ? (a0 + i) : (64 + a0 + i - 4);
            float4 v;
            unpack2(acc[i][0], v.x, v.y); unpack2(acc[i][1], v.z, v.w);
            *(float4*)&out[row * D + b0] = v;
            unpack2(acc[i][2], v.x, v.y); unpack2(acc[i][3], v.z, v.w);
            *(float4*)&out[row * D + b0 + 64] = v;
        }
    }
}

// ---------------------------------------------------------------------------
// Kernel 2 (fused combine + final), COALESCED layout:
//   Each CTA owns a 32-entry window (lane = consecutive entries -> every
//   warp-load hits exactly ONE 128B line). 8 warps x 32-b chunks cover all
//   256 partial blocks. Per-warp partials -> smem -> fixed-order cross-warp
//   sum -> contrib -> block reduce. Lower-triangle Gq/Gk loads predicated off.
//   Last block (atomic counter) merges block sums, subtracts diag, writes out.
// ---------------------------------------------------------------------------
__global__ __launch_bounds__(TPB) void combine_kernel(float* __restrict__ out,
                                                      int n)
{
    __shared__ float s_part[3][8][32];
    __shared__ float red[8];
    __shared__ int   s_last;

    const int tid  = threadIdx.x;
    const int lane = tid & 31, wrp = tid >> 5;
    const int e    = blockIdx.x * 32 + lane;        // this lane's entry
    const int r    = e >> 7, c = e & 127;
    const int i0   = (r & 63) >> 2, j0 = (c & 63) >> 2;
    const bool have_g = (i0 <= j0);                 // Gq/Gk tile stored?
    const int bbase = wrp * 32;                     // this warp's b-chunk

    float sq = 0.f, sk = 0.f, sc = 0.f;
    #pragma unroll 8
    for (int bb = 0; bb < 32; bb++) {
        const int b = bbase + bb;
        if (have_g) {
            sq += g_part[0][b][e];
            sk += g_part[1][b][e];
        }
        sc += g_part[2][b][e];
    }
    s_part[0][wrp][lane] = sq;
    s_part[1][wrp][lane] = sk;
    s_part[2][wrp][lane] = sc;
    __syncthreads();

    float contrib = 0.f;
    if (wrp == 0) {
        // fixed-order cross-warp sums (deterministic)
        float tq = 0.f, tk = 0.f, tc = 0.f;
        #pragma unroll
        for (int w8 = 0; w8 < 8; w8++) {
            tq += s_part[0][w8][lane];
            tk += s_part[1][w8][lane];
            tc += s_part[2][w8][lane];
        }
        const float wgt = (i0 == j0) ? 1.0f : 2.0f;
        contrib = wgt * (tq * tq + tk * tk) - 2.0f * tc * tc;
        // warp-reduce the 32 per-entry contribs
        #pragma unroll
        for (int o = 16; o; o >>= 1)
            contrib += __shfl_xor_sync(0xffffffffu, contrib, o);
        if (lane == 0) g_bsum[blockIdx.x] = contrib;
    }
    __syncthreads();

    // last-block final reduction (deterministic: fixed read order)
    if (tid == 0) {
        __threadfence();
        s_last = (atomicAdd(&g_count, 1) == CBLK - 1);
    }
    __syncthreads();
    if (s_last) {
        __threadfence();
        float v = g_bsum[tid] + g_bsum[tid + 256] - g_diag[tid];  // 256 each
        #pragma unroll
        for (int o = 16; o; o >>= 1) v += __shfl_xor_sync(0xffffffffu, v, o);
        if (lane == 0) red[wrp] = v;
        __syncthreads();
        if (wrp == 0) {
            float x = (lane < 8) ? red[lane] : 0.f;
            #pragma unroll
            for (int o = 4; o; o >>= 1) x += __shfl_xor_sync(0xffffffffu, x, o);
            if (lane == 0) {
                double denom = (double)n * (double)(n - 1);
                out[0] = (float)((double)x / denom);
                g_count = 0;                        // reset for next replay
            }
        }
    }
}

// ---------------------------------------------------------------------------
extern "C" void kernel_launch(void* const* d_in, const int* in_sizes, int n_in,
                              void* d_out, int out_size)
{
    const float* q = (const float*)d_in[0];
    const float* k = (const float*)d_in[1];
    const int n = in_sizes[0] / D;        // 8192

    gram_partial_kernel<<<n / ROWS, TPB>>>(q, k);
    combine_kernel<<<CBLK, TPB>>>((float*)d_out, n);
}